// round 12
// baseline (speedup 1.0000x reference)
#include <cuda_runtime.h>
#include <cuda_fp16.h>

#define HH 200
#define WW 320
#define CC 256
#define HWSZ (HH * WW)
#define RS 14
#define BINS (RS * RS)

// Scratch: transposed feature [H*W][C] fp16 (32.8 MB) + 196 bin maxima
__device__ __align__(128) static __half g_featT[(size_t)HWSZ * CC];
__device__ static unsigned g_bins[BINS];

// Monotonic float <-> uint encoding so atomicMax on unsigned == float max
__device__ __forceinline__ unsigned enc_f(float f) {
    unsigned u = __float_as_uint(f);
    return (u & 0x80000000u) ? ~u : (u | 0x80000000u);
}
__device__ __forceinline__ float dec_f(unsigned u) {
    return __uint_as_float((u & 0x80000000u) ? (u ^ 0x80000000u) : ~u);
}
#define ENC_NEG_INF 0x007FFFFFu  // enc_f(-inf)

// Transpose feature [C][H*W] fp32 -> g_featT [H*W][C] fp16.
// Tile 64ch x 32hw. Phase 1 converts to half2 at load time (4 STS.32/thread
// into a [32][33] uint tile, conflict-free). Phase 2: lane = (hw row, 8-ch
// slot) -> 4 LDS.32 + ONE STG.128; each 8-lane group writes 128B contiguous.
// Block (0,0) also initializes g_bins (no separate init launch).
__global__ void transpose_kernel(const float* __restrict__ A) {
    __shared__ unsigned sm[32][33];  // sm[hw][c_pair] = half2(c, c+1)
    int hw0 = blockIdx.x * 32;
    int c0 = blockIdx.y * 64;
    int tx = threadIdx.x, ty = threadIdx.y;  // 32 x 8

    if (blockIdx.x == 0 && blockIdx.y == 0) {
        int t = ty * 32 + tx;
        if (t < BINS) g_bins[t] = ENC_NEG_INF;
    }

    // Phase 1: thread covers hw=tx, channel pairs (ty*8 + 2j, +1), j=0..3.
    // Warp loads are 128B contiguous along hw for each channel row.
#pragma unroll
    for (int j = 0; j < 4; j++) {
        int cIdx = ty * 8 + j * 2;
        const float* p = A + (size_t)(c0 + cIdx) * HWSZ + hw0 + tx;
        float f0 = p[0];
        float f1 = p[HWSZ];
        __half2 h = __floats2half2_rn(f0, f1);
        sm[tx][cIdx >> 1] = *(unsigned*)&h;  // bank = (33*tx + ...) conflict-free
    }
    __syncthreads();

    // Phase 2: warp ty -> hw rows [4*ty, 4*ty+4); lane covers one 8-channel
    // slot (4 half2 words) of one row. Banks (hw + 4*col8 + i) mod 32 are all
    // distinct within the warp -> conflict-free LDS.32.
    int hw = ty * 4 + (tx >> 3);
    int col8 = tx & 7;
    unsigned u0 = sm[hw][4 * col8 + 0];
    unsigned u1 = sm[hw][4 * col8 + 1];
    unsigned u2 = sm[hw][4 * col8 + 2];
    unsigned u3 = sm[hw][4 * col8 + 3];
    uint4 v = make_uint4(u0, u1, u2, u3);
    *(uint4*)(g_featT + (size_t)(hw0 + hw) * CC + c0 + 8 * col8) = v;
}

// One warp per (roi, bin). A corner row is 256 fp16 = 512B = 32 lanes x 16B:
// exactly one LDG.128 per corner per lane. fp32 math after conversion.
// Identical to the 43.5us champion.
__global__ void roi_max_kernel(const float* __restrict__ rois, int R) {
    int warp = threadIdx.x >> 5;
    int lane = threadIdx.x & 31;
    int wid = blockIdx.x * (blockDim.x >> 5) + warp;
    if (wid >= R * BINS) return;
    int r = wid / BINS;
    int mn = wid - r * BINS;
    int m = mn / RS;
    int n = mn - m * RS;

    float r0 = __ldg(rois + 4 * r + 0);
    float r1 = __ldg(rois + 4 * r + 1);
    float r2 = __ldg(rois + 4 * r + 2);
    float r3 = __ldg(rois + 4 * r + 3);
    float sh = (r2 - r0) / (float)RS;
    float sw = (r3 - r1) / (float)RS;
    float yb = r0 + sh * (float)m;
    float xb = r1 + sw * (float)n;
    const float fr0 = 1.0f / 3.0f, fr1 = 2.0f / 3.0f;
    float ys[2] = {yb + sh * fr0, yb + sh * fr1};
    float xs[2] = {xb + sw * fr0, xb + sw * fr1};

    float vmax = __int_as_float(0xff800000);  // -inf

#pragma unroll
    for (int i = 0; i < 2; i++) {
#pragma unroll
        for (int j = 0; j < 2; j++) {
            float y = ys[i], x = xs[j];
            int yf = (int)floorf(y);
            int xf = (int)floorf(x);
            // clamp BEFORE weights (faithful to reference)
            int y1 = min(max(yf, 0), HH - 1);
            int y2 = min(max(yf + 1, 0), HH - 1);
            int x1 = min(max(xf, 0), WW - 1);
            int x2 = min(max(xf + 1, 0), WW - 1);
            float wxl = x - (float)x1;   // toward x2
            float wxh = (float)x2 - x;   // toward x1
            float wyl = y - (float)y1;
            float wyh = (float)y2 - y;

            const uint4* p11 = (const uint4*)(g_featT + (size_t)(y1 * WW + x1) * CC);
            const uint4* p12 = (const uint4*)(g_featT + (size_t)(y1 * WW + x2) * CC);
            const uint4* p21 = (const uint4*)(g_featT + (size_t)(y2 * WW + x1) * CC);
            const uint4* p22 = (const uint4*)(g_featT + (size_t)(y2 * WW + x2) * CC);

            uint4 A = p11[lane];
            uint4 B = p12[lane];
            uint4 C = p21[lane];
            uint4 D = p22[lane];
#pragma unroll
            for (int k = 0; k < 4; k++) {
                float2 fa = __half22float2(*(const __half2*)(&((const unsigned*)&A)[k]));
                float2 fb = __half22float2(*(const __half2*)(&((const unsigned*)&B)[k]));
                float2 fc = __half22float2(*(const __half2*)(&((const unsigned*)&C)[k]));
                float2 fd = __half22float2(*(const __half2*)(&((const unsigned*)&D)[k]));
                float v0 = (fa.x * wxh + fb.x * wxl) * wyh + (fc.x * wxh + fd.x * wxl) * wyl;
                float v1 = (fa.y * wxh + fb.y * wxl) * wyh + (fc.y * wxh + fd.y * wxl) * wyl;
                vmax = fmaxf(vmax, fmaxf(v0, v1));
            }
        }
    }

#pragma unroll
    for (int o = 16; o; o >>= 1)
        vmax = fmaxf(vmax, __shfl_xor_sync(0xffffffffu, vmax, o));
    if (lane == 0) atomicMax(&g_bins[mn], enc_f(vmax));
}

// Broadcast bin_max to out[R][C][14][14]. Each thread does 4 warp-contiguous
// float4 stores (block tile = 1024 float4s; store k at g0 + 256k keeps every
// STG.128 512B-contiguous per warp). Bin index advances by 11 mod 49 per k
// (256 mod 49 == 11), so the modulo is computed once.
__global__ void bcast_kernel(float* __restrict__ out, int total4) {
    __shared__ float4 s4[49];
    int t = threadIdx.x;
    if (t < BINS) ((float*)s4)[t] = dec_f(g_bins[t]);
    __syncthreads();
    int g0 = blockIdx.x * 1024 + t;
    int mq = g0 % 49;
#pragma unroll
    for (int k = 0; k < 4; k++) {
        int g = g0 + k * 256;
        if (g < total4) ((float4*)out)[g] = s4[mq];
        mq += 11;
        if (mq >= 49) mq -= 49;
    }
}

extern "C" void kernel_launch(void* const* d_in, const int* in_sizes, int n_in,
                              void* d_out, int out_size) {
    const float* feature = (const float*)d_in[0];
    const float* rois = (const float*)d_in[1];
    int R = in_sizes[1] / 4;

    dim3 tb(32, 8);
    dim3 tg(HWSZ / 32, CC / 64);
    transpose_kernel<<<tg, tb>>>(feature);

    int warps = R * BINS;
    int blocks = (warps + 7) / 8;
    roi_max_kernel<<<blocks, 256>>>(rois, R);

    int total4 = out_size / 4;
    bcast_kernel<<<(total4 + 1023) / 1024, 256>>>((float*)d_out, total4);
}

// round 13
// speedup vs baseline: 1.1834x; 1.1834x over previous
#include <cuda_runtime.h>
#include <cuda_fp16.h>

#define HH 200
#define WW 320
#define CC 256
#define HWSZ (HH * WW)
#define RS 14
#define BINS (RS * RS)

// Scratch: transposed feature [H*W][C] fp16 (32.8 MB) + 196 bin maxima
__device__ __align__(128) static __half g_featT[(size_t)HWSZ * CC];
__device__ static unsigned g_bins[BINS];

// Monotonic float <-> uint encoding so atomicMax on unsigned == float max
__device__ __forceinline__ unsigned enc_f(float f) {
    unsigned u = __float_as_uint(f);
    return (u & 0x80000000u) ? ~u : (u | 0x80000000u);
}
__device__ __forceinline__ float dec_f(unsigned u) {
    return __uint_as_float((u & 0x80000000u) ? (u ^ 0x80000000u) : ~u);
}
#define ENC_NEG_INF 0x007FFFFFu  // enc_f(-inf)

// Transpose feature [C][H*W] fp32 -> g_featT [H*W][C] fp16 (R12 version:
// half2 conversion at load, 4 STS.32 into [32][33] uint tile, phase 2 emits
// ONE STG.128 per thread). Block (0,0) initializes g_bins.
__global__ void transpose_kernel(const float* __restrict__ A) {
    __shared__ unsigned sm[32][33];  // sm[hw][c_pair] = half2(c, c+1)
    int hw0 = blockIdx.x * 32;
    int c0 = blockIdx.y * 64;
    int tx = threadIdx.x, ty = threadIdx.y;  // 32 x 8

    if (blockIdx.x == 0 && blockIdx.y == 0) {
        int t = ty * 32 + tx;
        if (t < BINS) g_bins[t] = ENC_NEG_INF;
    }

#pragma unroll
    for (int j = 0; j < 4; j++) {
        int cIdx = ty * 8 + j * 2;
        const float* p = A + (size_t)(c0 + cIdx) * HWSZ + hw0 + tx;
        float f0 = p[0];
        float f1 = p[HWSZ];
        __half2 h = __floats2half2_rn(f0, f1);
        sm[tx][cIdx >> 1] = *(unsigned*)&h;
    }
    __syncthreads();

    int hw = ty * 4 + (tx >> 3);
    int col8 = tx & 7;
    unsigned u0 = sm[hw][4 * col8 + 0];
    unsigned u1 = sm[hw][4 * col8 + 1];
    unsigned u2 = sm[hw][4 * col8 + 2];
    unsigned u3 = sm[hw][4 * col8 + 3];
    uint4 v = make_uint4(u0, u1, u2, u3);
    *(uint4*)(g_featT + (size_t)(hw0 + hw) * CC + c0 + 8 * col8) = v;
}

// Block = one (roi, m-row): 14 warps, warp = bin n. All warps share the same
// 2-4 corner y-rows and adjacent warps' x-columns overlap (bin step sw,
// pt step sw/3) -> L1 turns repeated 512B corner-row loads into hits.
// Per sample: corner row = 256 fp16 = 512B = 32 lanes x LDG.128.
__global__ void roi_max_kernel(const float* __restrict__ rois) {
    int lane = threadIdx.x & 31;
    int n = threadIdx.x >> 5;        // 0..13
    int r = blockIdx.x / RS;
    int m = blockIdx.x - r * RS;
    int mn = m * RS + n;

    float r0 = __ldg(rois + 4 * r + 0);
    float r1 = __ldg(rois + 4 * r + 1);
    float r2 = __ldg(rois + 4 * r + 2);
    float r3 = __ldg(rois + 4 * r + 3);
    float sh = (r2 - r0) / (float)RS;
    float sw = (r3 - r1) / (float)RS;
    float yb = r0 + sh * (float)m;
    float xb = r1 + sw * (float)n;
    const float fr0 = 1.0f / 3.0f, fr1 = 2.0f / 3.0f;
    float ys[2] = {yb + sh * fr0, yb + sh * fr1};
    float xs[2] = {xb + sw * fr0, xb + sw * fr1};

    float vmax = __int_as_float(0xff800000);  // -inf

#pragma unroll
    for (int i = 0; i < 2; i++) {
#pragma unroll
        for (int j = 0; j < 2; j++) {
            float y = ys[i], x = xs[j];
            int yf = (int)floorf(y);
            int xf = (int)floorf(x);
            // clamp BEFORE weights (faithful to reference)
            int y1 = min(max(yf, 0), HH - 1);
            int y2 = min(max(yf + 1, 0), HH - 1);
            int x1 = min(max(xf, 0), WW - 1);
            int x2 = min(max(xf + 1, 0), WW - 1);
            float wxl = x - (float)x1;   // toward x2
            float wxh = (float)x2 - x;   // toward x1
            float wyl = y - (float)y1;
            float wyh = (float)y2 - y;

            const uint4* p11 = (const uint4*)(g_featT + (size_t)(y1 * WW + x1) * CC);
            const uint4* p12 = (const uint4*)(g_featT + (size_t)(y1 * WW + x2) * CC);
            const uint4* p21 = (const uint4*)(g_featT + (size_t)(y2 * WW + x1) * CC);
            const uint4* p22 = (const uint4*)(g_featT + (size_t)(y2 * WW + x2) * CC);

            uint4 A = p11[lane];
            uint4 B = p12[lane];
            uint4 C = p21[lane];
            uint4 D = p22[lane];
#pragma unroll
            for (int k = 0; k < 4; k++) {
                float2 fa = __half22float2(*(const __half2*)(&((const unsigned*)&A)[k]));
                float2 fb = __half22float2(*(const __half2*)(&((const unsigned*)&B)[k]));
                float2 fc = __half22float2(*(const __half2*)(&((const unsigned*)&C)[k]));
                float2 fd = __half22float2(*(const __half2*)(&((const unsigned*)&D)[k]));
                float v0 = (fa.x * wxh + fb.x * wxl) * wyh + (fc.x * wxh + fd.x * wxl) * wyl;
                float v1 = (fa.y * wxh + fb.y * wxl) * wyh + (fc.y * wxh + fd.y * wxl) * wyl;
                vmax = fmaxf(vmax, fmaxf(v0, v1));
            }
        }
    }

#pragma unroll
    for (int o = 16; o; o >>= 1)
        vmax = fmaxf(vmax, __shfl_xor_sync(0xffffffffu, vmax, o));
    if (lane == 0) atomicMax(&g_bins[mn], enc_f(vmax));
}

// Broadcast bin_max to out[R][C][14][14]. Each thread does 4 warp-contiguous
// float4 stores; bin index advances by 11 mod 49 per store (256 mod 49 == 11).
__global__ void bcast_kernel(float* __restrict__ out, int total4) {
    __shared__ float4 s4[49];
    int t = threadIdx.x;
    if (t < BINS) ((float*)s4)[t] = dec_f(g_bins[t]);
    __syncthreads();
    int g0 = blockIdx.x * 1024 + t;
    int mq = g0 % 49;
#pragma unroll
    for (int k = 0; k < 4; k++) {
        int g = g0 + k * 256;
        if (g < total4) ((float4*)out)[g] = s4[mq];
        mq += 11;
        if (mq >= 49) mq -= 49;
    }
}

extern "C" void kernel_launch(void* const* d_in, const int* in_sizes, int n_in,
                              void* d_out, int out_size) {
    const float* feature = (const float*)d_in[0];
    const float* rois = (const float*)d_in[1];
    int R = in_sizes[1] / 4;

    dim3 tb(32, 8);
    dim3 tg(HWSZ / 32, CC / 64);
    transpose_kernel<<<tg, tb>>>(feature);

    roi_max_kernel<<<R * RS, RS * 32>>>(rois);

    int total4 = out_size / 4;
    bcast_kernel<<<(total4 + 1023) / 1024, 256>>>((float*)d_out, total4);
}